// round 15
// baseline (speedup 1.0000x reference)
#include <cuda_runtime.h>
#include <cuda_bf16.h>
#include <math.h>

#define NN 10000
#define NE 160000
#define HH 128
#define ER 20
#define RST 24
#define CUTOFF_F 5.0f
#define PI_F 3.14159265358979323846f

typedef unsigned long long u64;
typedef unsigned int u32;

// ---------------- device scratch ----------------
__device__ float g_ns [NN*HH];
__device__ float g_nvA[NN*3*HH];
__device__ float g_nvB[NN*3*HH];
__device__ float g_so [NN*3*HH];
__device__ float g_UV [NN*3*256];
__device__ float g_gate[NN*384];
__device__ __align__(16) float g_prbfc[NE*RST];
__device__ float4 g_pgeo[NE];
__device__ int   g_psrc[NE];
__device__ int   g_deg [NN];
__device__ int   g_off [NN+1];
__device__ int   g_cur [NN];
__device__ int   g_perm[NE];
// interleaved bf16 hi/lo activation buffers: u64 entry = {h2k,h2k+1,l2k,l2k+1}
__device__ __align__(16) u64 g_A0[NN*3*64 + 64];
__device__ __align__(16) u64 g_A1[NN*64 + 64];
// packed weights, wh/wl interleaved
#define WP_TOTAL 143360
__device__ __align__(16) u64 g_wp[2*WP_TOTAL];
#define OFF_MSGW1 0L
#define OFF_MSGW2 12288L
#define OFF_UVW   49152L
#define OFF_UPDW1 73728L
#define OFF_UPDW2 98304L
#define OFF_ROW1  135168L
#define OFF_ROW2  139264L

__device__ __forceinline__ float silu_f(float x){
    return x * (1.0f / (1.0f + __expf(-x)));
}
__device__ __forceinline__ u64 f2fma(u64 a, u64 b, u64 c){
    u64 d; asm("fma.rn.f32x2 %0, %1, %2, %3;" : "=l"(d) : "l"(a), "l"(b), "l"(c)); return d;
}
__device__ __forceinline__ u64 f2pack(float lo, float hi){
    u64 d; asm("mov.b64 %0, {%1, %2};" : "=l"(d) : "f"(lo), "f"(hi)); return d;
}
__device__ __forceinline__ float f2sum(u64 a){
    float x, y; asm("mov.b64 {%0, %1}, %2;" : "=f"(x), "=f"(y) : "l"(a)); return x + y;
}
__device__ __forceinline__ void mma16816(float* c, u32 a0,u32 a1,u32 a2,u32 a3, u32 b0,u32 b1){
    asm volatile("mma.sync.aligned.m16n8k16.row.col.f32.bf16.bf16.f32 "
        "{%0,%1,%2,%3}, {%4,%5,%6,%7}, {%8,%9}, {%0,%1,%2,%3};"
        : "+f"(c[0]),"+f"(c[1]),"+f"(c[2]),"+f"(c[3])
        : "r"(a0),"r"(a1),"r"(a2),"r"(a3),"r"(b0),"r"(b1));
}
__device__ __forceinline__ u32 packhl_h(float a, float b){
    __nv_bfloat16 h0 = __float2bfloat16_rn(a), h1 = __float2bfloat16_rn(b);
    return (u32)__bfloat16_as_ushort(h0) | ((u32)__bfloat16_as_ushort(h1) << 16);
}
__device__ __forceinline__ u32 packhl_l(float a, float b){
    __nv_bfloat16 h0 = __float2bfloat16_rn(a), h1 = __float2bfloat16_rn(b);
    float r0 = a - __bfloat162float(h0), r1 = b - __bfloat162float(h1);
    __nv_bfloat16 l0 = __float2bfloat16_rn(r0), l1 = __float2bfloat16_rn(r1);
    return (u32)__bfloat16_as_ushort(l0) | ((u32)__bfloat16_as_ushort(l1) << 16);
}
__device__ __forceinline__ void bf16w(u64* A, long flat, float v){
    unsigned short* p = (unsigned short*)(A + (flat >> 1));
    int s = (int)(flat & 1);
    __nv_bfloat16 h = __float2bfloat16_rn(v);
    p[s]     = __bfloat16_as_ushort(h);
    p[2 + s] = __bfloat16_as_ushort(__float2bfloat16_rn(v - __bfloat162float(h)));
}
__device__ __forceinline__ void cpa16(void* smem, const void* gmem){
    u32 sa = (u32)__cvta_generic_to_shared(smem);
    asm volatile("cp.async.ca.shared.global [%0], [%1], 16;" :: "r"(sa), "l"(gmem));
}

// ---------------- setup ----------------
__global__ void k_init(const int* __restrict__ z, const float* __restrict__ embed){
    int i = blockIdx.x*blockDim.x + threadIdx.x;
    if (i < NN*HH){
        int n = i >> 7; int j = i & 127;
        float v = embed[z[n]*HH + j];
        g_ns[i] = v;
        bf16w(g_A0, i, v);
    }
}
__global__ void k_zero(){
    int i = blockIdx.x*blockDim.x + threadIdx.x;
    if (i < NN*3*HH) g_nvA[i] = 0.0f;
    if (i < NN) g_deg[i] = 0;
}
__global__ void k_count(const int* __restrict__ edge){
    int e = blockIdx.x*blockDim.x + threadIdx.x;
    if (e < NE) atomicAdd(&g_deg[edge[2*e]], 1);
}
__global__ void k_scan(){
    __shared__ int sm[1024];
    __shared__ int base_s;
    int t = threadIdx.x;
    if (t == 0){ base_s = 0; g_off[0] = 0; }
    __syncthreads();
    for (int c0 = 0; c0 < NN; c0 += 1024){
        int i = c0 + t;
        int v = (i < NN) ? g_deg[i] : 0;
        sm[t] = v;
        __syncthreads();
        for (int ofs = 1; ofs < 1024; ofs <<= 1){
            int tv = (t >= ofs) ? sm[t-ofs] : 0;
            __syncthreads();
            sm[t] += tv;
            __syncthreads();
        }
        int inc = sm[t];
        int b = base_s;
        if (i < NN){ g_off[i+1] = b + inc; g_cur[i] = b + inc - v; }
        __syncthreads();
        if (t == 1023) base_s = b + sm[1023];
        __syncthreads();
    }
}
__global__ void k_scatter(const int* __restrict__ edge){
    int e = blockIdx.x*blockDim.x + threadIdx.x;
    if (e < NE){ int dst = edge[2*e]; int p = atomicAdd(&g_cur[dst], 1); g_perm[p] = e; }
}
__global__ void k_geom(const int* __restrict__ edge,
                       const float* __restrict__ dist, const float* __restrict__ diff){
    int p = blockIdx.x*blockDim.x + threadIdx.x;
    if (p >= NE) return;
    int e = g_perm[p];
    g_psrc[p] = edge[2*e + 1];
    float d = dist[e];
    float invd = 1.0f / d;
    float fc = (d < CUTOFF_F) ? 0.5f*(cosf(PI_F*d*(1.0f/CUTOFF_F)) + 1.0f) : 0.0f;
    g_pgeo[p] = make_float4(diff[3*e]*invd, diff[3*e+1]*invd, diff[3*e+2]*invd, fc);
    float s = fc * invd;
#pragma unroll
    for (int k = 0; k < ER; k++)
        g_prbfc[p*RST + k] = sinf(d * (float)(k+1) * (PI_F/CUTOFF_F)) * s;
#pragma unroll
    for (int k = ER; k < RST; k++) g_prbfc[p*RST + k] = 0.0f;
}

// one kernel packs ALL weight regions (flat index dispatch)
__device__ __forceinline__ void pack_one(const float* S, const float* S2,
        int K, int N, int N1, long per, long ridx, long gidx){
    int l = (int)(ridx / per); long r = ridx % per;
    int m = (int)(r & 3); long r2 = r >> 2;
    int n = (int)(r2 % N); int s = (int)(r2 / N);
    int k0 = s*16 + 2*m;
    const float* P; int nn, Nw;
    if (S2 && n >= N1){ P = S2 + (long)l*K*(N-N1); nn = n - N1; Nw = N - N1; }
    else if (S2)      { P = S  + (long)l*K*N1;     nn = n;      Nw = N1; }
    else              { P = S  + (long)l*K*N;      nn = n;      Nw = N; }
    float w0 = P[(long)(k0  )*Nw + nn];
    float w1 = P[(long)(k0+1)*Nw + nn];
    float w8 = P[(long)(k0+8)*Nw + nn];
    float w9 = P[(long)(k0+9)*Nw + nn];
    u64 hh = (u64)packhl_h(w0, w1) | ((u64)packhl_h(w8, w9) << 32);
    u64 ll = (u64)packhl_l(w0, w1) | ((u64)packhl_l(w8, w9) << 32);
    g_wp[gidx*2    ] = hh;
    g_wp[gidx*2 + 1] = ll;
}
__global__ void k_packall(const float* mw1, const float* mw2,
                          const float* uUw, const float* uVw,
                          const float* uw1, const float* uw2,
                          const float* rw1, const float* rw2){
    long i = (long)blockIdx.x*blockDim.x + threadIdx.x;
    if (i >= WP_TOTAL) return;
    if      (i < OFF_MSGW2) pack_one(mw1, 0,   128, 128, 0,   4096,  i - OFF_MSGW1, i);
    else if (i < OFF_UVW)   pack_one(mw2, 0,   128, 384, 0,   12288, i - OFF_MSGW2, i);
    else if (i < OFF_UPDW1) pack_one(uUw, uVw, 128, 256, 128, 8192,  i - OFF_UVW,   i);
    else if (i < OFF_UPDW2) pack_one(uw1, 0,   256, 128, 0,   8192,  i - OFF_UPDW1, i);
    else if (i < OFF_ROW1)  pack_one(uw2, 0,   128, 384, 0,   12288, i - OFF_UPDW2, i);
    else if (i < OFF_ROW2)  pack_one(rw1, 0,   128, 128, 0,   4096,  i - OFF_ROW1,  i);
    else                    pack_one(rw2, 0,   128, 128, 0,   4096,  i - OFF_ROW2,  i);
}

// ---------------- tensor-core GEMM: 32x128 tile, cp.async double-buffered weights ----------------
__global__ __launch_bounds__(256) void k_mma(
        long woff, int M, int K, int Ntot, int asel, int mode, int osel,
        const float* __restrict__ bias, const float* __restrict__ bias2,
        float* __restrict__ Cext){
    __shared__ __align__(16) ulonglong2 sw[2][512];      // 16KB
    int tid = threadIdx.x;
    int lane = tid & 31, w = tid >> 5;
    int mw = w & 1, nw = w >> 1;
    int m0 = blockIdx.x*32 + mw*16;
    int nbase = blockIdx.y*128 + nw*32;
    const u64* A = asel ? g_A1 : g_A0;
    int Kw2 = K >> 1;
    int r0 = m0 + (lane >> 2);
    int r1 = r0 + 8;
    int r0c = r0 < M ? r0 : M-1;
    int r1c = r1 < M ? r1 : M-1;
    int kq = lane & 3;
    // contiguous weight source for this block: entries (s*Ntot + nb0 + colL)*4 + m
    const ulonglong2* W0 = ((const ulonglong2*)g_wp) + woff + (long)(blockIdx.y*128)*4;
    float c[4][4];
#pragma unroll
    for (int nt = 0; nt < 4; nt++){ c[nt][0]=0.f; c[nt][1]=0.f; c[nt][2]=0.f; c[nt][3]=0.f; }
    int nsteps = K >> 4;
    const long ar0 = (long)r0c*Kw2 + kq;
    const long ar1 = (long)r1c*Kw2 + kq;
    // smem read index for this thread (per nt): (nw*32 + nt*8 + lane>>2)*4 + kq
    int swi = (nw*32 + (lane >> 2))*4 + kq;
    // prologue: stage s=0
    {
        const ulonglong2* src = W0;
        cpa16(&sw[0][tid], src + tid);
        cpa16(&sw[0][tid + 256], src + tid + 256);
        asm volatile("cp.async.commit_group;");
    }
    for (int s = 0; s < nsteps; s++){
        // issue A loads early (land during wait/barrier)
        u64 a00 = A[ar0 + (long)s*8];
        u64 a01 = A[ar1 + (long)s*8];
        u64 a02 = A[ar0 + (long)s*8 + 4];
        u64 a03 = A[ar1 + (long)s*8 + 4];
        if (s + 1 < nsteps){
            const ulonglong2* src = W0 + (long)(s+1)*Ntot*4;
            cpa16(&sw[(s+1)&1][tid], src + tid);
            cpa16(&sw[(s+1)&1][tid + 256], src + tid + 256);
            asm volatile("cp.async.commit_group;");
            asm volatile("cp.async.wait_group 1;");
        } else {
            asm volatile("cp.async.wait_group 0;");
        }
        __syncthreads();
        const ulonglong2* wb = sw[s & 1];
        u32 ah0 = (u32)a00, al0 = (u32)(a00 >> 32);
        u32 ah1 = (u32)a01, al1 = (u32)(a01 >> 32);
        u32 ah2 = (u32)a02, al2 = (u32)(a02 >> 32);
        u32 ah3 = (u32)a03, al3 = (u32)(a03 >> 32);
#pragma unroll
        for (int nt = 0; nt < 4; nt++){
            ulonglong2 wp = wb[swi + nt*32];
            u32 bh0 = (u32)wp.x, bh1 = (u32)(wp.x >> 32);
            u32 bl0 = (u32)wp.y, bl1 = (u32)(wp.y >> 32);
            mma16816(c[nt], ah0, ah1, ah2, ah3, bh0, bh1);
            mma16816(c[nt], al0, al1, al2, al3, bh0, bh1);
            mma16816(c[nt], ah0, ah1, ah2, ah3, bl0, bl1);
        }
        __syncthreads();
    }
    int colq = kq*2;
#pragma unroll
    for (int nt = 0; nt < 4; nt++){
        int col = nbase + nt*8 + colq;
        float b0v, b1v;
        if (bias2 != 0 && col >= 128){ b0v = bias2[col-128]; b1v = bias2[col-127]; }
        else { b0v = bias[col]; b1v = bias[col+1]; }
        float v00 = c[nt][0] + b0v, v01 = c[nt][1] + b1v;
        float v10 = c[nt][2] + b0v, v11 = c[nt][3] + b1v;
        if (mode == 1){
            v00 = silu_f(v00); v01 = silu_f(v01);
            v10 = silu_f(v10); v11 = silu_f(v11);
            int pw = col >> 1;
            int Kw2o = Ntot >> 1;
            if (r0 < M){
                u64 val = (u64)packhl_h(v00, v01) | ((u64)packhl_l(v00, v01) << 32);
                g_A1[(long)r0*Kw2o + pw] = val;
            }
            if (r1 < M){
                u64 val = (u64)packhl_h(v10, v11) | ((u64)packhl_l(v10, v11) << 32);
                g_A1[(long)r1*Kw2o + pw] = val;
            }
        } else {
            float* C = (osel == 0) ? g_so : (osel == 1) ? g_UV : (osel == 2) ? g_gate : Cext;
            if (r0 < M){ float2 v = make_float2(v00, v01); *(float2*)&C[(long)r0*Ntot + col] = v; }
            if (r1 < M){ float2 v = make_float2(v10, v11); *(float2*)&C[(long)r1*Ntot + col] = v; }
        }
    }
}

// ---------------- edge message pass (NPB=1, pipelined gathers) ----------------
__global__ __launch_bounds__(128) void k_edge(int l,
        const float* __restrict__ fw_, const float* __restrict__ fb_){
    const float* Wf = fw_ + l*ER*3*HH;
    const float* Bf = fb_ + l*3*HH;
    const float* nv_in  = (l == 1) ? g_nvB : g_nvA;
    float*       nv_out = (l == 1) ? g_nvA : g_nvB;
    int j = threadIdx.x;
    u64 wf0[ER/2], wf1[ER/2], wf2[ER/2];
#pragma unroll
    for (int k = 0; k < ER/2; k++){
        wf0[k] = f2pack(Wf[(2*k)*384 + j],       Wf[(2*k+1)*384 + j]);
        wf1[k] = f2pack(Wf[(2*k)*384 + 128 + j], Wf[(2*k+1)*384 + 128 + j]);
        wf2[k] = f2pack(Wf[(2*k)*384 + 256 + j], Wf[(2*k+1)*384 + 256 + j]);
    }
    float bf0 = Bf[j], bf1 = Bf[128+j], bf2 = Bf[256+j];
    int n = blockIdx.x;
    int s = g_off[n], e1 = g_off[n+1];
    float acc_s = 0.f, av0 = 0.f, av1 = 0.f, av2 = 0.f;
    if (s < e1){
        int src = g_psrc[s];
        float4 geo = g_pgeo[s];
        float sb0 = g_so[(long)src*384 + j];
        float sb1 = g_so[(long)src*384 + 128 + j];
        float sb2 = g_so[(long)src*384 + 256 + j];
        float nb0 = nv_in[(long)src*384 + j];
        float nb1 = nv_in[(long)src*384 + 128 + j];
        float nb2 = nv_in[(long)src*384 + 256 + j];
        for (int p = s; p < e1; p++){
            int pn = (p+1 < e1) ? p+1 : p;
            int nsrc = g_psrc[pn];
            float4 ngeo = g_pgeo[pn];
            float fc = geo.w;
            u64 f0a = f2pack(bf0*fc, 0.f);
            u64 f1a = f2pack(bf1*fc, 0.f);
            u64 f2a = f2pack(bf2*fc, 0.f);
            const ulonglong2* r2 = (const ulonglong2*)&g_prbfc[(long)p*RST];
#pragma unroll
            for (int q = 0; q < 5; q++){
                ulonglong2 rr = r2[q];
                f0a = f2fma(rr.x, wf0[2*q],   f0a);
                f0a = f2fma(rr.y, wf0[2*q+1], f0a);
                f1a = f2fma(rr.x, wf1[2*q],   f1a);
                f1a = f2fma(rr.y, wf1[2*q+1], f1a);
                f2a = f2fma(rr.x, wf2[2*q],   f2a);
                f2a = f2fma(rr.y, wf2[2*q+1], f2a);
            }
            float nsb0 = g_so[(long)nsrc*384 + j];
            float nsb1 = g_so[(long)nsrc*384 + 128 + j];
            float nsb2 = g_so[(long)nsrc*384 + 256 + j];
            float nnb0 = nv_in[(long)nsrc*384 + j];
            float nnb1 = nv_in[(long)nsrc*384 + 128 + j];
            float nnb2 = nv_in[(long)nsrc*384 + 256 + j];
            float gsv = f2sum(f0a) * sb0;
            float gev = f2sum(f1a) * sb1;
            float ms  = f2sum(f2a) * sb2;
            acc_s += ms;
            av0 += nb0*gsv + gev*geo.x;
            av1 += nb1*gsv + gev*geo.y;
            av2 += nb2*gsv + gev*geo.z;
            src = nsrc; geo = ngeo;
            sb0 = nsb0; sb1 = nsb1; sb2 = nsb2;
            nb0 = nnb0; nb1 = nnb1; nb2 = nnb2;
        }
    }
    g_ns[n*128 + j] += acc_s;
    float o0 = nv_in[(long)n*384 + j      ] + av0;
    float o1 = nv_in[(long)n*384 + 128 + j] + av1;
    float o2 = nv_in[(long)n*384 + 256 + j] + av2;
    nv_out[(long)n*384 + j      ] = o0;
    nv_out[(long)n*384 + 128 + j] = o1;
    nv_out[(long)n*384 + 256 + j] = o2;
    bf16w(g_A0, (long)n*384 + j,       o0);
    bf16w(g_A0, (long)n*384 + 128 + j, o1);
    bf16w(g_A0, (long)n*384 + 256 + j, o2);
}

// build upd-MLP input (||Vv|| | ns) into interleaved A0 [NN rows, K=256]
__global__ __launch_bounds__(128) void k_prep(){
    int j = threadIdx.x;
    const int NPB = 4;
    for (int ni = 0; ni < NPB; ni++){
        int n = blockIdx.x*NPB + ni;
        float V0 = g_UV[(long)(n*3+0)*256 + 128 + j];
        float V1 = g_UV[(long)(n*3+1)*256 + 128 + j];
        float V2 = g_UV[(long)(n*3+2)*256 + 128 + j];
        float nm = sqrtf(V0*V0 + V1*V1 + V2*V2);
        bf16w(g_A0, (long)n*256 + j,       nm);
        bf16w(g_A0, (long)n*256 + 128 + j, g_ns[n*128 + j]);
    }
}

// apply gates; emits interleaved bf16(ns)
__global__ __launch_bounds__(128) void k_apply(int l){
    float* nv = (l == 1) ? g_nvA : g_nvB;
    int j = threadIdx.x;
    const int NPB = 4;
    for (int ni = 0; ni < NPB; ni++){
        int n = blockIdx.x*NPB + ni;
        float avv = g_gate[(long)n*384 + j];
        float asv = g_gate[(long)n*384 + 128 + j];
        float ass = g_gate[(long)n*384 + 256 + j];
        float U0 = g_UV[(long)(n*3+0)*256 + j];
        float U1 = g_UV[(long)(n*3+1)*256 + j];
        float U2 = g_UV[(long)(n*3+2)*256 + j];
        float V0 = g_UV[(long)(n*3+0)*256 + 128 + j];
        float V1 = g_UV[(long)(n*3+1)*256 + 128 + j];
        float V2 = g_UV[(long)(n*3+2)*256 + 128 + j];
        float duv = U0*V0 + U1*V1 + U2*V2;
        nv[(long)n*384 + j      ] += avv*U0;
        nv[(long)n*384 + 128 + j] += avv*U1;
        nv[(long)n*384 + 256 + j] += avv*U2;
        float ns_new = g_ns[n*128 + j] + asv*duv + ass;
        g_ns[n*128 + j] = ns_new;
        bf16w(g_A0, (long)n*128 + j, ns_new);
    }
}

// ---------------- launch ----------------
extern "C" void kernel_launch(void* const* d_in, const int* in_sizes, int n_in,
                              void* d_out, int out_size){
    const int*   z         = (const int*)  d_in[0];
    const int*   edge      = (const int*)  d_in[1];
    const float* edge_diff = (const float*)d_in[2];
    const float* edge_dist = (const float*)d_in[3];
    const float* embed     = (const float*)d_in[4];
    const float* mfw = (const float*)d_in[5];
    const float* mfb = (const float*)d_in[6];
    const float* mw1 = (const float*)d_in[7];
    const float* mb1 = (const float*)d_in[8];
    const float* mw2 = (const float*)d_in[9];
    const float* mb2 = (const float*)d_in[10];
    const float* uUw = (const float*)d_in[11];
    const float* uUb = (const float*)d_in[12];
    const float* uVw = (const float*)d_in[13];
    const float* uVb = (const float*)d_in[14];
    const float* uw1 = (const float*)d_in[15];
    const float* ub1 = (const float*)d_in[16];
    const float* uw2 = (const float*)d_in[17];
    const float* ub2 = (const float*)d_in[18];
    const float* rw1 = (const float*)d_in[19];
    const float* rb1 = (const float*)d_in[20];
    const float* rw2 = (const float*)d_in[21];
    const float* rb2 = (const float*)d_in[22];
    float* out = (float*)d_out;

    const int GM  = (NN + 31)/32;        // 313
    const int GUV = (NN*3 + 31)/32;      // 938

    k_packall<<<(WP_TOTAL + 255)/256, 256>>>(mw1, mw2, uUw, uVw, uw1, uw2, rw1, rw2);
    k_init<<<(NN*HH + 255)/256, 256>>>(z, embed);
    k_zero<<<(NN*3*HH + 255)/256, 256>>>();
    k_mma<<<dim3(GM,1), 256>>>(OFF_MSGW1, NN, 128, 128, 0, 1, 0, mb1, 0, 0);

    k_count<<<(NE + 255)/256, 256>>>(edge);
    k_scan<<<1, 1024>>>();
    k_scatter<<<(NE + 255)/256, 256>>>(edge);
    k_geom<<<(NE + 255)/256, 256>>>(edge, edge_dist, edge_diff);

    for (int l = 0; l < 3; l++){
        if (l > 0)
            k_mma<<<dim3(GM,1), 256>>>(OFF_MSGW1 + l*4096L, NN, 128, 128, 0, 1, 0, mb1 + l*128, 0, 0);
        k_mma<<<dim3(GM,3), 256>>>(OFF_MSGW2 + l*12288L, NN, 128, 384, 1, 0, 0, mb2 + l*384, 0, 0);
        k_edge<<<NN, 128>>>(l, mfw, mfb);
        k_mma<<<dim3(GUV,2), 256>>>(OFF_UVW + l*8192L, NN*3, 128, 256, 0, 0, 1, uUb + l*128, uVb + l*128, 0);
        k_prep<<<NN/4, 128>>>();
        k_mma<<<dim3(GM,1), 256>>>(OFF_UPDW1 + l*8192L, NN, 256, 128, 0, 1, 0, ub1 + l*128, 0, 0);
        k_mma<<<dim3(GM,3), 256>>>(OFF_UPDW2 + l*12288L, NN, 128, 384, 1, 0, 2, ub2 + l*384, 0, 0);
        k_apply<<<NN/4, 128>>>(l);
    }
    k_mma<<<dim3(GM,1), 256>>>(OFF_ROW1, NN, 128, 128, 0, 1, 0, rb1, 0, 0);
    k_mma<<<dim3(GM,1), 256>>>(OFF_ROW2, NN, 128, 128, 1, 0, 3, rb2, 0, out);
}

// round 16
// speedup vs baseline: 1.0828x; 1.0828x over previous
#include <cuda_runtime.h>
#include <cuda_bf16.h>
#include <math.h>

#define NN 10000
#define NE 160000
#define HH 128
#define ER 20
#define RST 24
#define CUTOFF_F 5.0f
#define PI_F 3.14159265358979323846f

typedef unsigned long long u64;
typedef unsigned int u32;

// ---------------- device scratch ----------------
__device__ float g_ns [NN*HH];
__device__ float g_nvA[NN*3*HH];
__device__ float g_nvB[NN*3*HH];
__device__ float g_so [NN*3*HH];
__device__ float g_UV [NN*3*256];
__device__ float g_gate[NN*384];
__device__ __align__(16) float g_prbfc[NE*RST];
__device__ float4 g_pgeo[NE];
__device__ int   g_psrc[NE];
__device__ int   g_deg [NN];
__device__ int   g_off [NN+1];
__device__ int   g_cur [NN];
__device__ int   g_perm[NE];
// interleaved bf16 hi/lo activation buffers: u64 entry = {h2k,h2k+1,l2k,l2k+1}
__device__ __align__(16) u64 g_A0[NN*3*64 + 64];
__device__ __align__(16) u64 g_A1[NN*64 + 64];
// packed weights, wh/wl interleaved
#define WP_TOTAL 143360
__device__ __align__(16) u64 g_wp[2*WP_TOTAL];
#define OFF_MSGW1 0L
#define OFF_MSGW2 12288L
#define OFF_UVW   49152L
#define OFF_UPDW1 73728L
#define OFF_UPDW2 98304L
#define OFF_ROW1  135168L
#define OFF_ROW2  139264L

__device__ __forceinline__ float silu_f(float x){
    return x * (1.0f / (1.0f + __expf(-x)));
}
__device__ __forceinline__ u64 f2fma(u64 a, u64 b, u64 c){
    u64 d; asm("fma.rn.f32x2 %0, %1, %2, %3;" : "=l"(d) : "l"(a), "l"(b), "l"(c)); return d;
}
__device__ __forceinline__ u64 f2pack(float lo, float hi){
    u64 d; asm("mov.b64 %0, {%1, %2};" : "=l"(d) : "f"(lo), "f"(hi)); return d;
}
__device__ __forceinline__ float f2sum(u64 a){
    float x, y; asm("mov.b64 {%0, %1}, %2;" : "=f"(x), "=f"(y) : "l"(a)); return x + y;
}
__device__ __forceinline__ void mma16816(float* c, u32 a0,u32 a1,u32 a2,u32 a3, u32 b0,u32 b1){
    asm volatile("mma.sync.aligned.m16n8k16.row.col.f32.bf16.bf16.f32 "
        "{%0,%1,%2,%3}, {%4,%5,%6,%7}, {%8,%9}, {%0,%1,%2,%3};"
        : "+f"(c[0]),"+f"(c[1]),"+f"(c[2]),"+f"(c[3])
        : "r"(a0),"r"(a1),"r"(a2),"r"(a3),"r"(b0),"r"(b1));
}
__device__ __forceinline__ u32 packhl_h(float a, float b){
    __nv_bfloat16 h0 = __float2bfloat16_rn(a), h1 = __float2bfloat16_rn(b);
    return (u32)__bfloat16_as_ushort(h0) | ((u32)__bfloat16_as_ushort(h1) << 16);
}
__device__ __forceinline__ u32 packhl_l(float a, float b){
    __nv_bfloat16 h0 = __float2bfloat16_rn(a), h1 = __float2bfloat16_rn(b);
    float r0 = a - __bfloat162float(h0), r1 = b - __bfloat162float(h1);
    __nv_bfloat16 l0 = __float2bfloat16_rn(r0), l1 = __float2bfloat16_rn(r1);
    return (u32)__bfloat16_as_ushort(l0) | ((u32)__bfloat16_as_ushort(l1) << 16);
}
__device__ __forceinline__ void bf16w(u64* A, long flat, float v){
    unsigned short* p = (unsigned short*)(A + (flat >> 1));
    int s = (int)(flat & 1);
    __nv_bfloat16 h = __float2bfloat16_rn(v);
    p[s]     = __bfloat16_as_ushort(h);
    p[2 + s] = __bfloat16_as_ushort(__float2bfloat16_rn(v - __bfloat162float(h)));
}

// ---------------- setup ----------------
__global__ void k_init(const int* __restrict__ z, const float* __restrict__ embed){
    int i = blockIdx.x*blockDim.x + threadIdx.x;
    if (i < NN*HH){
        int n = i >> 7; int j = i & 127;
        float v = embed[z[n]*HH + j];
        g_ns[i] = v;
        bf16w(g_A0, i, v);
    }
}
__global__ void k_zero(){
    int i = blockIdx.x*blockDim.x + threadIdx.x;
    if (i < NN*3*HH) g_nvA[i] = 0.0f;
    if (i < NN) g_deg[i] = 0;
}
__global__ void k_count(const int* __restrict__ edge){
    int e = blockIdx.x*blockDim.x + threadIdx.x;
    if (e < NE) atomicAdd(&g_deg[edge[2*e]], 1);
}
__global__ void k_scan(){
    __shared__ int sm[1024];
    __shared__ int base_s;
    int t = threadIdx.x;
    if (t == 0){ base_s = 0; g_off[0] = 0; }
    __syncthreads();
    for (int c0 = 0; c0 < NN; c0 += 1024){
        int i = c0 + t;
        int v = (i < NN) ? g_deg[i] : 0;
        sm[t] = v;
        __syncthreads();
        for (int ofs = 1; ofs < 1024; ofs <<= 1){
            int tv = (t >= ofs) ? sm[t-ofs] : 0;
            __syncthreads();
            sm[t] += tv;
            __syncthreads();
        }
        int inc = sm[t];
        int b = base_s;
        if (i < NN){ g_off[i+1] = b + inc; g_cur[i] = b + inc - v; }
        __syncthreads();
        if (t == 1023) base_s = b + sm[1023];
        __syncthreads();
    }
}
__global__ void k_scatter(const int* __restrict__ edge){
    int e = blockIdx.x*blockDim.x + threadIdx.x;
    if (e < NE){ int dst = edge[2*e]; int p = atomicAdd(&g_cur[dst], 1); g_perm[p] = e; }
}
__global__ void k_geom(const int* __restrict__ edge,
                       const float* __restrict__ dist, const float* __restrict__ diff){
    int p = blockIdx.x*blockDim.x + threadIdx.x;
    if (p >= NE) return;
    int e = g_perm[p];
    g_psrc[p] = edge[2*e + 1];
    float d = dist[e];
    float invd = 1.0f / d;
    float fc = (d < CUTOFF_F) ? 0.5f*(cosf(PI_F*d*(1.0f/CUTOFF_F)) + 1.0f) : 0.0f;
    g_pgeo[p] = make_float4(diff[3*e]*invd, diff[3*e+1]*invd, diff[3*e+2]*invd, fc);
    float s = fc * invd;
#pragma unroll
    for (int k = 0; k < ER; k++)
        g_prbfc[p*RST + k] = sinf(d * (float)(k+1) * (PI_F/CUTOFF_F)) * s;
#pragma unroll
    for (int k = ER; k < RST; k++) g_prbfc[p*RST + k] = 0.0f;
}

// one kernel packs ALL weight regions (flat index dispatch)
__device__ __forceinline__ void pack_one(const float* S, const float* S2,
        int K, int N, int N1, long per, long ridx, long gidx){
    int l = (int)(ridx / per); long r = ridx % per;
    int m = (int)(r & 3); long r2 = r >> 2;
    int n = (int)(r2 % N); int s = (int)(r2 / N);
    int k0 = s*16 + 2*m;
    const float* P; int nn, Nw;
    if (S2 && n >= N1){ P = S2 + (long)l*K*(N-N1); nn = n - N1; Nw = N - N1; }
    else if (S2)      { P = S  + (long)l*K*N1;     nn = n;      Nw = N1; }
    else              { P = S  + (long)l*K*N;      nn = n;      Nw = N; }
    float w0 = P[(long)(k0  )*Nw + nn];
    float w1 = P[(long)(k0+1)*Nw + nn];
    float w8 = P[(long)(k0+8)*Nw + nn];
    float w9 = P[(long)(k0+9)*Nw + nn];
    u64 hh = (u64)packhl_h(w0, w1) | ((u64)packhl_h(w8, w9) << 32);
    u64 ll = (u64)packhl_l(w0, w1) | ((u64)packhl_l(w8, w9) << 32);
    g_wp[gidx*2    ] = hh;
    g_wp[gidx*2 + 1] = ll;
}
__global__ void k_packall(const float* mw1, const float* mw2,
                          const float* uUw, const float* uVw,
                          const float* uw1, const float* uw2,
                          const float* rw1, const float* rw2){
    long i = (long)blockIdx.x*blockDim.x + threadIdx.x;
    if (i >= WP_TOTAL) return;
    if      (i < OFF_MSGW2) pack_one(mw1, 0,   128, 128, 0,   4096,  i - OFF_MSGW1, i);
    else if (i < OFF_UVW)   pack_one(mw2, 0,   128, 384, 0,   12288, i - OFF_MSGW2, i);
    else if (i < OFF_UPDW1) pack_one(uUw, uVw, 128, 256, 128, 8192,  i - OFF_UVW,   i);
    else if (i < OFF_UPDW2) pack_one(uw1, 0,   256, 128, 0,   8192,  i - OFF_UPDW1, i);
    else if (i < OFF_ROW1)  pack_one(uw2, 0,   128, 384, 0,   12288, i - OFF_UPDW2, i);
    else if (i < OFF_ROW2)  pack_one(rw1, 0,   128, 128, 0,   4096,  i - OFF_ROW1,  i);
    else                    pack_one(rw2, 0,   128, 128, 0,   4096,  i - OFF_ROW2,  i);
}

// ---------------- tensor-core GEMM (R14-exact: 32-row x 128-col tile) ----------------
__global__ __launch_bounds__(256) void k_mma(
        long woff, int M, int K, int Ntot, int asel, int mode, int osel,
        const float* __restrict__ bias, const float* __restrict__ bias2,
        float* __restrict__ Cext){
    int tid = threadIdx.x;
    int lane = tid & 31, w = tid >> 5;
    int mw = w & 1, nw = w >> 1;
    int m0 = blockIdx.x*32 + mw*16;
    int nbase = blockIdx.y*128 + nw*32;
    const u64* A = asel ? g_A1 : g_A0;
    int Kw2 = K >> 1;
    int r0 = m0 + (lane >> 2);
    int r1 = r0 + 8;
    int r0c = r0 < M ? r0 : M-1;
    int r1c = r1 < M ? r1 : M-1;
    int kq = lane & 3;
    float c[4][4];
#pragma unroll
    for (int nt = 0; nt < 4; nt++){ c[nt][0]=0.f; c[nt][1]=0.f; c[nt][2]=0.f; c[nt][3]=0.f; }
    int nsteps = K >> 4;
    const long ar0 = (long)r0c*Kw2 + kq;
    const long ar1 = (long)r1c*Kw2 + kq;
#pragma unroll 4
    for (int s = 0; s < nsteps; s++){
        u64 a00 = A[ar0 + s*8];
        u64 a01 = A[ar1 + s*8];
        u64 a02 = A[ar0 + s*8 + 4];
        u64 a03 = A[ar1 + s*8 + 4];
        u32 ah0 = (u32)a00, al0 = (u32)(a00 >> 32);
        u32 ah1 = (u32)a01, al1 = (u32)(a01 >> 32);
        u32 ah2 = (u32)a02, al2 = (u32)(a02 >> 32);
        u32 ah3 = (u32)a03, al3 = (u32)(a03 >> 32);
        long wrow = woff + ((long)s*Ntot + nbase)*4 + kq;
#pragma unroll
        for (int nt = 0; nt < 4; nt++){
            long wi = wrow + (long)(nt*8 + (lane >> 2))*4;
            ulonglong2 wp = *(const ulonglong2*)&g_wp[wi*2];
            u32 bh0 = (u32)wp.x, bh1 = (u32)(wp.x >> 32);
            u32 bl0 = (u32)wp.y, bl1 = (u32)(wp.y >> 32);
            mma16816(c[nt], ah0, ah1, ah2, ah3, bh0, bh1);
            mma16816(c[nt], al0, al1, al2, al3, bh0, bh1);
            mma16816(c[nt], ah0, ah1, ah2, ah3, bl0, bl1);
        }
    }
    int colq = kq*2;
#pragma unroll
    for (int nt = 0; nt < 4; nt++){
        int col = nbase + nt*8 + colq;
        float b0v, b1v;
        if (bias2 != 0 && col >= 128){ b0v = bias2[col-128]; b1v = bias2[col-127]; }
        else { b0v = bias[col]; b1v = bias[col+1]; }
        float v00 = c[nt][0] + b0v, v01 = c[nt][1] + b1v;
        float v10 = c[nt][2] + b0v, v11 = c[nt][3] + b1v;
        if (mode == 1){
            v00 = silu_f(v00); v01 = silu_f(v01);
            v10 = silu_f(v10); v11 = silu_f(v11);
            int pw = col >> 1;
            int Kw2o = Ntot >> 1;
            if (r0 < M){
                u64 val = (u64)packhl_h(v00, v01) | ((u64)packhl_l(v00, v01) << 32);
                g_A1[(long)r0*Kw2o + pw] = val;
            }
            if (r1 < M){
                u64 val = (u64)packhl_h(v10, v11) | ((u64)packhl_l(v10, v11) << 32);
                g_A1[(long)r1*Kw2o + pw] = val;
            }
        } else {
            float* C = (osel == 0) ? g_so : (osel == 1) ? g_UV : (osel == 2) ? g_gate : Cext;
            if (r0 < M){ float2 v = make_float2(v00, v01); *(float2*)&C[(long)r0*Ntot + col] = v; }
            if (r1 < M){ float2 v = make_float2(v10, v11); *(float2*)&C[(long)r1*Ntot + col] = v; }
        }
    }
}

// ---------------- edge message pass: 256 thr, two 128-thread groups split even/odd edges ----------------
__global__ __launch_bounds__(256) void k_edge(int l,
        const float* __restrict__ fw_, const float* __restrict__ fb_){
    const float* Wf = fw_ + l*ER*3*HH;
    const float* Bf = fb_ + l*3*HH;
    const float* nv_in  = (l == 1) ? g_nvB : g_nvA;
    float*       nv_out = (l == 1) ? g_nvA : g_nvB;
    __shared__ float sm[4][128];
    int tid = threadIdx.x;
    int g = tid >> 7;          // 0 or 1
    int j = tid & 127;
    u64 wf0[ER/2], wf1[ER/2], wf2[ER/2];
#pragma unroll
    for (int k = 0; k < ER/2; k++){
        wf0[k] = f2pack(Wf[(2*k)*384 + j],       Wf[(2*k+1)*384 + j]);
        wf1[k] = f2pack(Wf[(2*k)*384 + 128 + j], Wf[(2*k+1)*384 + 128 + j]);
        wf2[k] = f2pack(Wf[(2*k)*384 + 256 + j], Wf[(2*k+1)*384 + 256 + j]);
    }
    float bf0 = Bf[j], bf1 = Bf[128+j], bf2 = Bf[256+j];
    int n = blockIdx.x;
    int s0 = g_off[n], e1 = g_off[n+1];
    float acc_s = 0.f, av0 = 0.f, av1 = 0.f, av2 = 0.f;
    int p0 = s0 + g;                            // this group's first edge
    if (p0 < e1){
        int src = g_psrc[p0];
        float4 geo = g_pgeo[p0];
        float sb0 = g_so[(long)src*384 + j];
        float sb1 = g_so[(long)src*384 + 128 + j];
        float sb2 = g_so[(long)src*384 + 256 + j];
        float nb0 = nv_in[(long)src*384 + j];
        float nb1 = nv_in[(long)src*384 + 128 + j];
        float nb2 = nv_in[(long)src*384 + 256 + j];
        for (int p = p0; p < e1; p += 2){
            int pn = (p+2 < e1) ? p+2 : p;
            int nsrc = g_psrc[pn];
            float4 ngeo = g_pgeo[pn];
            float fc = geo.w;
            u64 f0a = f2pack(bf0*fc, 0.f);
            u64 f1a = f2pack(bf1*fc, 0.f);
            u64 f2a = f2pack(bf2*fc, 0.f);
            const ulonglong2* r2 = (const ulonglong2*)&g_prbfc[(long)p*RST];
#pragma unroll
            for (int q = 0; q < 5; q++){
                ulonglong2 rr = r2[q];
                f0a = f2fma(rr.x, wf0[2*q],   f0a);
                f0a = f2fma(rr.y, wf0[2*q+1], f0a);
                f1a = f2fma(rr.x, wf1[2*q],   f1a);
                f1a = f2fma(rr.y, wf1[2*q+1], f1a);
                f2a = f2fma(rr.x, wf2[2*q],   f2a);
                f2a = f2fma(rr.y, wf2[2*q+1], f2a);
            }
            float nsb0 = g_so[(long)nsrc*384 + j];
            float nsb1 = g_so[(long)nsrc*384 + 128 + j];
            float nsb2 = g_so[(long)nsrc*384 + 256 + j];
            float nnb0 = nv_in[(long)nsrc*384 + j];
            float nnb1 = nv_in[(long)nsrc*384 + 128 + j];
            float nnb2 = nv_in[(long)nsrc*384 + 256 + j];
            float gsv = f2sum(f0a) * sb0;
            float gev = f2sum(f1a) * sb1;
            float ms  = f2sum(f2a) * sb2;
            acc_s += ms;
            av0 += nb0*gsv + gev*geo.x;
            av1 += nb1*gsv + gev*geo.y;
            av2 += nb2*gsv + gev*geo.z;
            src = nsrc; geo = ngeo;
            sb0 = nsb0; sb1 = nsb1; sb2 = nsb2;
            nb0 = nnb0; nb1 = nnb1; nb2 = nnb2;
        }
    }
    if (g == 1){
        sm[0][j] = acc_s; sm[1][j] = av0; sm[2][j] = av1; sm[3][j] = av2;
    }
    __syncthreads();
    if (g == 0){
        acc_s += sm[0][j]; av0 += sm[1][j]; av1 += sm[2][j]; av2 += sm[3][j];
        g_ns[n*128 + j] += acc_s;
        float o0 = nv_in[(long)n*384 + j      ] + av0;
        float o1 = nv_in[(long)n*384 + 128 + j] + av1;
        float o2 = nv_in[(long)n*384 + 256 + j] + av2;
        nv_out[(long)n*384 + j      ] = o0;
        nv_out[(long)n*384 + 128 + j] = o1;
        nv_out[(long)n*384 + 256 + j] = o2;
        bf16w(g_A0, (long)n*384 + j,       o0);
        bf16w(g_A0, (long)n*384 + 128 + j, o1);
        bf16w(g_A0, (long)n*384 + 256 + j, o2);
    }
}

// build upd-MLP input (||Vv|| | ns) into interleaved A0 [NN rows, K=256]
__global__ __launch_bounds__(128) void k_prep(){
    int j = threadIdx.x;
    const int NPB = 4;
    for (int ni = 0; ni < NPB; ni++){
        int n = blockIdx.x*NPB + ni;
        float V0 = g_UV[(long)(n*3+0)*256 + 128 + j];
        float V1 = g_UV[(long)(n*3+1)*256 + 128 + j];
        float V2 = g_UV[(long)(n*3+2)*256 + 128 + j];
        float nm = sqrtf(V0*V0 + V1*V1 + V2*V2);
        bf16w(g_A0, (long)n*256 + j,       nm);
        bf16w(g_A0, (long)n*256 + 128 + j, g_ns[n*128 + j]);
    }
}

// apply gates; emits interleaved bf16(ns)
__global__ __launch_bounds__(128) void k_apply(int l){
    float* nv = (l == 1) ? g_nvA : g_nvB;
    int j = threadIdx.x;
    const int NPB = 4;
    for (int ni = 0; ni < NPB; ni++){
        int n = blockIdx.x*NPB + ni;
        float avv = g_gate[(long)n*384 + j];
        float asv = g_gate[(long)n*384 + 128 + j];
        float ass = g_gate[(long)n*384 + 256 + j];
        float U0 = g_UV[(long)(n*3+0)*256 + j];
        float U1 = g_UV[(long)(n*3+1)*256 + j];
        float U2 = g_UV[(long)(n*3+2)*256 + j];
        float V0 = g_UV[(long)(n*3+0)*256 + 128 + j];
        float V1 = g_UV[(long)(n*3+1)*256 + 128 + j];
        float V2 = g_UV[(long)(n*3+2)*256 + 128 + j];
        float duv = U0*V0 + U1*V1 + U2*V2;
        nv[(long)n*384 + j      ] += avv*U0;
        nv[(long)n*384 + 128 + j] += avv*U1;
        nv[(long)n*384 + 256 + j] += avv*U2;
        float ns_new = g_ns[n*128 + j] + asv*duv + ass;
        g_ns[n*128 + j] = ns_new;
        bf16w(g_A0, (long)n*128 + j, ns_new);
    }
}

// ---------------- launch ----------------
extern "C" void kernel_launch(void* const* d_in, const int* in_sizes, int n_in,
                              void* d_out, int out_size){
    const int*   z         = (const int*)  d_in[0];
    const int*   edge      = (const int*)  d_in[1];
    const float* edge_diff = (const float*)d_in[2];
    const float* edge_dist = (const float*)d_in[3];
    const float* embed     = (const float*)d_in[4];
    const float* mfw = (const float*)d_in[5];
    const float* mfb = (const float*)d_in[6];
    const float* mw1 = (const float*)d_in[7];
    const float* mb1 = (const float*)d_in[8];
    const float* mw2 = (const float*)d_in[9];
    const float* mb2 = (const float*)d_in[10];
    const float* uUw = (const float*)d_in[11];
    const float* uUb = (const float*)d_in[12];
    const float* uVw = (const float*)d_in[13];
    const float* uVb = (const float*)d_in[14];
    const float* uw1 = (const float*)d_in[15];
    const float* ub1 = (const float*)d_in[16];
    const float* uw2 = (const float*)d_in[17];
    const float* ub2 = (const float*)d_in[18];
    const float* rw1 = (const float*)d_in[19];
    const float* rb1 = (const float*)d_in[20];
    const float* rw2 = (const float*)d_in[21];
    const float* rb2 = (const float*)d_in[22];
    float* out = (float*)d_out;

    const int GM  = (NN + 31)/32;        // 313
    const int GUV = (NN*3 + 31)/32;      // 938

    k_packall<<<(WP_TOTAL + 255)/256, 256>>>(mw1, mw2, uUw, uVw, uw1, uw2, rw1, rw2);
    k_init<<<(NN*HH + 255)/256, 256>>>(z, embed);
    k_zero<<<(NN*3*HH + 255)/256, 256>>>();
    k_mma<<<dim3(GM,1), 256>>>(OFF_MSGW1, NN, 128, 128, 0, 1, 0, mb1, 0, 0);

    k_count<<<(NE + 255)/256, 256>>>(edge);
    k_scan<<<1, 1024>>>();
    k_scatter<<<(NE + 255)/256, 256>>>(edge);
    k_geom<<<(NE + 255)/256, 256>>>(edge, edge_dist, edge_diff);

    for (int l = 0; l < 3; l++){
        if (l > 0)
            k_mma<<<dim3(GM,1), 256>>>(OFF_MSGW1 + l*4096L, NN, 128, 128, 0, 1, 0, mb1 + l*128, 0, 0);
        k_mma<<<dim3(GM,3), 256>>>(OFF_MSGW2 + l*12288L, NN, 128, 384, 1, 0, 0, mb2 + l*384, 0, 0);
        k_edge<<<NN, 256>>>(l, mfw, mfb);
        k_mma<<<dim3(GUV,2), 256>>>(OFF_UVW + l*8192L, NN*3, 128, 256, 0, 0, 1, uUb + l*128, uVb + l*128, 0);
        k_prep<<<NN/4, 128>>>();
        k_mma<<<dim3(GM,1), 256>>>(OFF_UPDW1 + l*8192L, NN, 256, 128, 0, 1, 0, ub1 + l*128, 0, 0);
        k_mma<<<dim3(GM,3), 256>>>(OFF_UPDW2 + l*12288L, NN, 128, 384, 1, 0, 2, ub2 + l*384, 0, 0);
        k_apply<<<NN/4, 128>>>(l);
    }
    k_mma<<<dim3(GM,1), 256>>>(OFF_ROW1, NN, 128, 128, 0, 1, 0, rb1, 0, 0);
    k_mma<<<dim3(GM,1), 256>>>(OFF_ROW2, NN, 128, 128, 1, 0, 3, rb2, 0, out);
}